// round 12
// baseline (speedup 1.0000x reference)
#include <cuda_runtime.h>

// LSTM T=4096, B=2048, I=2, H=4, L=4. Gate order i,f,g,o.
// lane = b*8 + l*2 + u : b = batch-in-warp (4), l = layer (4), u = half (2).
// Each thread owns 2 hidden units (8 gate rows) of (batch, layer): cell update
// thread-local for both units. Loop-carried chain crosses ONE partner shuffle;
// the 4 layer-handoff shuffles have a full body of slack (skewed wavefront).
// z computed as packed f32x2 gate pairs {i,f},{g,o} per unit. All activations
// tanh.approx (sigmoid = 0.5*tanh(x/2)+0.5, weights pre-scaled 0.5).
// 4-warp blocks, 128 blocks -> 1 warp per SMSP on 128 SMs (no contention).

#define TT 4096
#define BB 2048

typedef unsigned long long u64;

__device__ __forceinline__ float tanhx(float x) {
    float y; asm("tanh.approx.f32 %0, %1;" : "=f"(y) : "f"(x)); return y;
}
__device__ __forceinline__ u64 pack2(float lo, float hi) {
    u64 r; asm("mov.b64 %0, {%1, %2};" : "=l"(r) : "f"(lo), "f"(hi)); return r;
}
__device__ __forceinline__ u64 pdup(float v) {
    u64 r; asm("mov.b64 %0, {%1, %1};" : "=l"(r) : "f"(v)); return r;
}
__device__ __forceinline__ void unpack2(u64 v, float& lo, float& hi) {
    asm("mov.b64 {%0, %1}, %2;" : "=f"(lo), "=f"(hi) : "l"(v));
}
__device__ __forceinline__ u64 fma2(u64 a, u64 b, u64 c) {
    u64 d; asm("fma.rn.f32x2 %0, %1, %2, %3;" : "=l"(d) : "l"(a), "l"(b), "l"(c));
    return d;
}
__device__ __forceinline__ u64 mul2(u64 a, u64 b) {
    u64 d; asm("mul.rn.f32x2 %0, %1, %2;" : "=l"(d) : "l"(a), "l"(b));
    return d;
}
__device__ __forceinline__ u64 add2(u64 a, u64 b) {
    u64 d; asm("add.rn.f32x2 %0, %1, %2;" : "=l"(d) : "l"(a), "l"(b));
    return d;
}

__global__ __launch_bounds__(128) void lstm_kernel(
    const float* __restrict__ x,     // (T, B, 2)
    const float* __restrict__ h0g,   // (L, B, 4)
    const float* __restrict__ c0g,   // (L, B, 4)
    const float* __restrict__ Wih0,  // (16, 2)
    const float* __restrict__ Wr,    // (3, 16, 4)  W_ih layers 1..3
    const float* __restrict__ Whh,   // (4, 16, 4)
    const float* __restrict__ bih,   // (4, 16)
    const float* __restrict__ bhh,   // (4, 16)
    float* __restrict__ out)         // ys (T,B,4) ++ hT (L,B,4) ++ cT (L,B,4)
{
    const int lane  = threadIdx.x & 31;
    const int warp  = threadIdx.x >> 5;
    const int b     = lane >> 3;              // batch-in-warp 0..3
    const int l     = (lane >> 1) & 3;        // layer 0..3
    const int u     = lane & 1;               // half: units {2u, 2u+1}
    const int batch = blockIdx.x * 16 + warp * 4 + b;

    const bool l0 = (l == 0);
    const bool l3 = (l == 3);

    // layer-handoff source lanes (prev layer's two halves)
    const int ps0 = (lane - 2 - u) & 31;      // u=0 lane of layer l-1
    const int ps1 = (ps0 + 1) & 31;           // u=1 lane of layer l-1

    // ---- packed weights: [local unit u_][gate pair t][input k] ----
    // t=0 -> gates (i,f) both sigmoid (scale 0.5); t=1 -> (g,o) = (1.0, 0.5).
    // wh columns permuted so k indexes {own_lo, own_hi, partner_lo, partner_hi}.
    // win columns natural (handoff q0..q3 arrive in unit order); for l==0,
    // k=0,1 carry Wih0 (x enters through hin slots 0,1), k=2,3 zero.
    u64 winP[2][2][4], whP[2][2][4], bzP[2][2];
#pragma unroll
    for (int u_ = 0; u_ < 2; u_++) {
        const int j = 2 * u + u_;             // global unit
#pragma unroll
        for (int t = 0; t < 2; t++) {
            const int   rA = (t ? 8 : 0) + j;   // i_j or g_j
            const int   rB = (t ? 12 : 4) + j;  // f_j or o_j
            const float sA = t ? 1.0f : 0.5f;
            const float sB = 0.5f;
#pragma unroll
            for (int k = 0; k < 4; k++) {
                const int col = (k < 2) ? (2 * u + k) : (2 * (1 - u) + (k - 2));
                whP[u_][t][k] = pack2(Whh[(l * 16 + rA) * 4 + col] * sA,
                                      Whh[(l * 16 + rB) * 4 + col] * sB);
                float wa, wb;
                if (!l0) {
                    wa = Wr[((l - 1) * 16 + rA) * 4 + k] * sA;
                    wb = Wr[((l - 1) * 16 + rB) * 4 + k] * sB;
                } else if (k < 2) {
                    wa = Wih0[rA * 2 + k] * sA;
                    wb = Wih0[rB * 2 + k] * sB;
                } else {
                    wa = 0.f; wb = 0.f;
                }
                winP[u_][t][k] = pack2(wa, wb);
            }
            bzP[u_][t] = pack2((bih[l * 16 + rA] + bhh[l * 16 + rA]) * sA,
                               (bih[l * 16 + rB] + bhh[l * 16 + rB]) * sB);
        }
    }

    // ---- states: this thread's two units ----
    float h_lo, h_hi, c_lo, c_hi;
    {
        float2 hv = *reinterpret_cast<const float2*>(
            h0g + (l * BB + batch) * 4 + 2 * u);
        h_lo = hv.x; h_hi = hv.y;
        float2 cv = *reinterpret_cast<const float2*>(
            c0g + (l * BB + batch) * 4 + 2 * u);
        c_lo = cv.x; c_hi = cv.y;
    }

    float* __restrict__ hso = out + (size_t)TT * BB * 4;
    float* __restrict__ cso = hso + (size_t)4 * BB * 4;
    float2* __restrict__ ysp =
        reinterpret_cast<float2*>(out) + (size_t)batch * 2 + u - (size_t)3 * BB * 2;

    // ---- x stream: rotating regs + running prefetch pointer (depth 3) ----
    const float2* __restrict__ xbase = reinterpret_cast<const float2*>(x) + batch;
    const float2* __restrict__ xend  = xbase + (size_t)TT * BB;
    const float2* __restrict__ xp    = xbase + (size_t)3 * BB;
    float2 xa = xbase[0];
    float2 xn = xbase[(size_t)1 * BB];
    float2 xm = xbase[(size_t)2 * BB];

    // ---- pre-loop: populate hP / hinP from initial h (no x rotate) ----
    u64 hP[4], hinP[4];
    {
        float plo = __shfl_xor_sync(0xffffffffu, h_lo, 1);
        float phi = __shfl_xor_sync(0xffffffffu, h_hi, 1);
        float q0  = __shfl_sync(0xffffffffu, h_lo, ps0, 32);
        float q1  = __shfl_sync(0xffffffffu, h_hi, ps0, 32);
        float q2  = __shfl_sync(0xffffffffu, h_lo, ps1, 32);
        float q3  = __shfl_sync(0xffffffffu, h_hi, ps1, 32);
        hP[0] = pdup(h_lo); hP[1] = pdup(h_hi);
        hP[2] = pdup(plo);  hP[3] = pdup(phi);
        hinP[0] = pdup(l0 ? xa.x : q0);
        hinP[1] = pdup(l0 ? xa.y : q1);
        hinP[2] = pdup(q2); hinP[3] = pdup(q3);
    }

    auto body = [&](int s, bool masked) {
        bool act = masked ? ((unsigned)(s - l) < (unsigned)TT) : true;

        // ---- z pre-activations: 4 packed gate pairs ----
        float zi[2], zf[2], zg[2], zo[2];
#pragma unroll
        for (int u_ = 0; u_ < 2; u_++) {
#pragma unroll
            for (int t = 0; t < 2; t++) {
                u64 uu = bzP[u_][t];
#pragma unroll
                for (int k = 0; k < 4; k++)
                    uu = fma2(winP[u_][t][k], hinP[k], uu);
                u64 vv = mul2(whP[u_][t][0], hP[0]);
#pragma unroll
                for (int k = 1; k < 4; k++)
                    vv = fma2(whP[u_][t][k], hP[k], vv);
                float a2, b2;
                unpack2(add2(uu, vv), a2, b2);
                if (t == 0) { zi[u_] = a2; zf[u_] = b2; }
                else        { zg[u_] = a2; zo[u_] = b2; }
            }
        }

        // ---- activations + cell updates (both units thread-local) ----
        float hn_lo, hn_hi, cn_lo, cn_hi;
        {
            float si = fmaf(tanhx(zi[0]), 0.5f, 0.5f);
            float sf = fmaf(tanhx(zf[0]), 0.5f, 0.5f);
            float tg = tanhx(zg[0]);
            float so = fmaf(tanhx(zo[0]), 0.5f, 0.5f);
            cn_lo = fmaf(sf, c_lo, si * tg);
            hn_lo = so * tanhx(cn_lo);
        }
        {
            float si = fmaf(tanhx(zi[1]), 0.5f, 0.5f);
            float sf = fmaf(tanhx(zf[1]), 0.5f, 0.5f);
            float tg = tanhx(zg[1]);
            float so = fmaf(tanhx(zo[1]), 0.5f, 0.5f);
            cn_hi = fmaf(sf, c_hi, si * tg);
            hn_hi = so * tanhx(cn_hi);
        }

        if (act) {
            c_lo = cn_lo; c_hi = cn_hi;
            h_lo = hn_lo; h_hi = hn_hi;
            if (l3) *ysp = make_float2(h_lo, h_hi);   // one predicated STG.64
        }
        ysp += (size_t)BB * 2;

        // ---- tail: shuffles (handoff has a body of slack) + x rotate ----
        float plo = __shfl_xor_sync(0xffffffffu, h_lo, 1);
        float phi = __shfl_xor_sync(0xffffffffu, h_hi, 1);
        float q0  = __shfl_sync(0xffffffffu, h_lo, ps0, 32);
        float q1  = __shfl_sync(0xffffffffu, h_hi, ps0, 32);
        float q2  = __shfl_sync(0xffffffffu, h_lo, ps1, 32);
        float q3  = __shfl_sync(0xffffffffu, h_hi, ps1, 32);

        xa = xn; xn = xm;
        xm = (xp < xend) ? *xp : xa;
        xp += BB;

        hP[0] = pdup(h_lo); hP[1] = pdup(h_hi);
        hP[2] = pdup(plo);  hP[3] = pdup(phi);
        hinP[0] = pdup(l0 ? xa.x : q0);
        hinP[1] = pdup(l0 ? xa.y : q1);
        hinP[2] = pdup(q2); hinP[3] = pdup(q3);
    };

    body(0, true); body(1, true); body(2, true);
#pragma unroll 2
    for (int s = 3; s < TT; s++) body(s, false);
    body(TT, true); body(TT + 1, true); body(TT + 2, true);

    // ---- final hT / cT (each lane stores its 2 units) ----
    *reinterpret_cast<float2*>(hso + (l * BB + batch) * 4 + 2 * u) =
        make_float2(h_lo, h_hi);
    *reinterpret_cast<float2*>(cso + (l * BB + batch) * 4 + 2 * u) =
        make_float2(c_lo, c_hi);
}

extern "C" void kernel_launch(void* const* d_in, const int* in_sizes, int n_in,
                              void* d_out, int out_size) {
    (void)in_sizes; (void)n_in; (void)out_size;
    const float* x    = (const float*)d_in[0];
    const float* h0   = (const float*)d_in[1];
    const float* c0   = (const float*)d_in[2];
    const float* Wih0 = (const float*)d_in[3];
    const float* Wr   = (const float*)d_in[4];
    const float* Whh  = (const float*)d_in[5];
    const float* bih  = (const float*)d_in[6];
    const float* bhh  = (const float*)d_in[7];
    // 16 batches per block (4 warps x 4), 128 blocks -> 1 warp/SMSP on 128 SMs
    lstm_kernel<<<BB / 16, 128>>>(x, h0, c0, Wih0, Wr, Whh, bih, bhh,
                                  (float*)d_out);
}

// round 13
// speedup vs baseline: 1.4955x; 1.4955x over previous
#include <cuda_runtime.h>

// LSTM T=4096, B=2048, I=2, H=4, L=4. Gate order i,f,g,o.
// lane = b*16 + l*4 + j (R10 layout): each lane computes all 4 gate rows of
// its unit locally; 7 independent shuffles per body. Skewed wavefront:
// body(s) runs layer l at step s-l. All activations tanh.approx.
// KEY CHANGE vs R10: x is software-pipelined in two 8-slot register banks
// with alternating roles (16-body load->use distance, no register rotation),
// so the global-load latency that capped every previous round is fully hidden.

#define TT 4096
#define BB 2048

__device__ __forceinline__ float tanhx(float x) {
    float y; asm("tanh.approx.f32 %0, %1;" : "=f"(y) : "f"(x)); return y;
}

__global__ __launch_bounds__(128) void lstm_kernel(
    const float* __restrict__ x,     // (T, B, 2)
    const float* __restrict__ h0g,   // (L, B, 4)
    const float* __restrict__ c0g,   // (L, B, 4)
    const float* __restrict__ Wih0,  // (16, 2)
    const float* __restrict__ Wr,    // (3, 16, 4)  W_ih layers 1..3
    const float* __restrict__ Whh,   // (4, 16, 4)
    const float* __restrict__ bih,   // (4, 16)
    const float* __restrict__ bhh,   // (4, 16)
    float* __restrict__ out)         // ys (T,B,4) ++ hT (L,B,4) ++ cT (L,B,4)
{
    const int lane  = threadIdx.x & 31;
    const int warp  = threadIdx.x >> 5;
    const int b     = lane >> 4;              // batch sub-index in warp 0..1
    const int l     = (lane >> 2) & 3;        // layer 0..3
    const int j     = lane & 3;               // hidden unit 0..3
    const int batch = blockIdx.x * 8 + warp * 2 + b;

    // handoff source lanes (previous layer's quad)
    const int ps0 = lane - 4;
    const int ps1 = (lane - 4) ^ 1;
    const int ps2 = (lane - 4) ^ 2;
    const int ps3 = (lane - 4) ^ 3;

    // ---- weights: 4 gate rows of unit j in layer l ----
    // pre-scale: sigmoid gates (i,f,o) -> 0.5 (sigmoid via tanh), g -> 1.
    float win[4][4], wh[4][4], bz[4];
#pragma unroll
    for (int g4 = 0; g4 < 4; g4++) {
        const int   row = g4 * 4 + j;         // i_j, f_j, g_j, o_j
        const float sc  = (g4 == 2) ? 1.0f : 0.5f;
        if (l == 0) {
            win[g4][0] = Wih0[row * 2 + 0] * sc;
            win[g4][1] = Wih0[row * 2 + 1] * sc;
            win[g4][2] = 0.f; win[g4][3] = 0.f;
        } else {
#pragma unroll
            for (int m = 0; m < 4; m++)
                win[g4][m] = Wr[((l - 1) * 16 + row) * 4 + (j ^ m)] * sc;
        }
#pragma unroll
        for (int m = 0; m < 4; m++)
            wh[g4][m] = Whh[(l * 16 + row) * 4 + (j ^ m)] * sc;
        bz[g4] = (bih[l * 16 + row] + bhh[l * 16 + row]) * sc;
    }

    // ---- states ----
    float hown[4], hin[4], c;
#pragma unroll
    for (int m = 0; m < 4; m++) {
        hown[m] = h0g[(l * BB + batch) * 4 + (j ^ m)];
        hin[m]  = 0.f;
    }
    c = c0g[(l * BB + batch) * 4 + j];

    float* __restrict__ hso = out + (size_t)TT * BB * 4;
    float* __restrict__ cso = hso + (size_t)4 * BB * 4;
    float4* __restrict__ ysp = reinterpret_cast<float4*>(out) + batch - 3 * BB;

    // ---- x banks: two 8-slot register banks, 16-body load->use distance ----
    const float2* __restrict__ xb2 = reinterpret_cast<const float2*>(x) + batch;
    float2 xA[8], xB[8];
#pragma unroll
    for (int k = 0; k < 8; k++) xA[k] = xb2[(size_t)k * BB];
#pragma unroll
    for (int k = 0; k < 8; k++) xB[k] = xb2[(size_t)(8 + k) * BB];

    auto body = [&](int s, float2 xv, bool masked) {
        // ---- four gate pre-activations (two depth-4 chains each) ----
        float z[4];
#pragma unroll
        for (int g4 = 0; g4 < 4; g4++) {
            float u = fmaf(win[g4][0], hin[0],
                      fmaf(win[g4][1], hin[1], bz[g4]));
            u = fmaf(win[g4][2], hin[2], u);
            u = fmaf(win[g4][3], hin[3], u);
            float v = fmaf(wh[g4][0], hown[0], wh[g4][1] * hown[1]);
            v = fmaf(wh[g4][2], hown[2], v);
            v = fmaf(wh[g4][3], hown[3], v);
            z[g4] = u + v;
        }

        // ---- activations (all MUFU tanh) ----
        float si = fmaf(tanhx(z[0]), 0.5f, 0.5f);   // sigma(i)
        float sf = fmaf(tanhx(z[1]), 0.5f, 0.5f);   // sigma(f)
        float tg = tanhx(z[2]);                     // tanh(g)
        float so = fmaf(tanhx(z[3]), 0.5f, 0.5f);   // sigma(o)

        float cn = fmaf(sf, c, si * tg);
        float th = tanhx(cn);                       // tanh(c)
        float h  = so * th;

        // ---- 7 independent shuffles, all sourced from h ----
        float h1 = __shfl_xor_sync(0xffffffffu, h, 1);
        float h2 = __shfl_xor_sync(0xffffffffu, h, 2);
        float h3 = __shfl_xor_sync(0xffffffffu, h, 3);
        float p0 = __shfl_sync(0xffffffffu, h, ps0, 16);
        float p1 = __shfl_sync(0xffffffffu, h, ps1, 16);
        float p2 = __shfl_sync(0xffffffffu, h, ps2, 16);
        float p3 = __shfl_sync(0xffffffffu, h, ps3, 16);

        bool act  = masked ? ((unsigned)(s - l)     < (unsigned)TT) : true;
        bool actp = masked ? ((unsigned)(s + 1 - l) < (unsigned)TT) : true;

        if (act) {
            c = cn;
            hown[0] = h;  hown[1] = h1; hown[2] = h2; hown[3] = h3;
            if (l == 3 && j == 0)
                *ysp = make_float4(h, h1, h2, h3);
        }
        ysp += BB;

        if (l == 0) { hin[0] = xv.x; hin[1] = xv.y; }
        else if (actp) { hin[0] = p0; hin[1] = p1; hin[2] = p2; hin[3] = p3; }
    };

    // NOTE on hin: R10 consumed x[s] in body(s) via pre-loaded xa; here body(s)
    // installs x[s+1] into hin for body(s+1), and body(0)'s x[0] is installed
    // in this pre-loop step:
    if (l == 0) { hin[0] = xA[0].x; hin[1] = xA[0].y; }

    // ---- steady loop: chunks of 16, two banks in alternating roles ----
    // Invariant at chunk top: xA = x[s0..s0+8), xB = x[s0+8..s0+16).
    // body(s0+k) consumes bank slot k AND refills it with x[s0+16+k] (slack 16).
#pragma unroll 1
    for (int s0 = 0; s0 < TT; s0 += 16) {
        const bool masked = (s0 == 0);
#pragma unroll
        for (int k = 0; k < 8; k++) {
            const int tl = s0 + 16 + k;
            float2 xv = xA[k];
            xA[k] = xb2[(size_t)(tl < TT ? tl : TT - 1) * BB];
            // body(s) installs x[s+1]: slot for s0+k+1 (bank A slot k+1 or
            // bank B slot 0) is still unrefilled, so pass the NEXT x value.
            float2 xnext = (k < 7) ? xA[k + 1] : xB[0];
            (void)xv;
            body(s0 + k, xnext, masked);
        }
#pragma unroll
        for (int k = 0; k < 8; k++) {
            const int tl = s0 + 24 + k;
            xB[k] = xb2[(size_t)(tl < TT ? tl : TT - 1) * BB];
            float2 xnext = (k < 7) ? xB[k + 1] : xA[0];
            body(s0 + 8 + k, xnext, masked);
        }
    }
    // ---- drain: bodies TT, TT+1, TT+2 (layer 0 inactive; x unused) ----
    body(TT,     make_float2(0.f, 0.f), true);
    body(TT + 1, make_float2(0.f, 0.f), true);
    body(TT + 2, make_float2(0.f, 0.f), true);

    // ---- final hT / cT ----
    if (j == 0)   // hown[m] = h_m natural order for j==0
        *reinterpret_cast<float4*>(hso + (l * BB + batch) * 4) =
            make_float4(hown[0], hown[1], hown[2], hown[3]);
    cso[(l * BB + batch) * 4 + j] = c;
}

extern "C" void kernel_launch(void* const* d_in, const int* in_sizes, int n_in,
                              void* d_out, int out_size) {
    (void)in_sizes; (void)n_in; (void)out_size;
    const float* x    = (const float*)d_in[0];
    const float* h0   = (const float*)d_in[1];
    const float* c0   = (const float*)d_in[2];
    const float* Wih0 = (const float*)d_in[3];
    const float* Wr   = (const float*)d_in[4];
    const float* Whh  = (const float*)d_in[5];
    const float* bih  = (const float*)d_in[6];
    const float* bhh  = (const float*)d_in[7];
    // 8 batches per block (4 warps x 2), 256 blocks
    lstm_kernel<<<BB / 8, 128>>>(x, h0, c0, Wih0, Wr, Whh, bih, bhh,
                                 (float*)d_out);
}

// round 15
// speedup vs baseline: 1.7839x; 1.1928x over previous
#include <cuda_runtime.h>

// LSTM T=4096, B=2048, I=2, H=4, L=4. Gate order i,f,g,o.
// lane = b*16 + l*4 + j: each lane computes all 4 gate rows of its unit
// locally; 7 independent shuffles per body. Skewed wavefront: body(s) runs
// layer l at step s-l. All activations tanh.approx.
// x pipeline: 8-slot register bank, load->use distance 8 bodies (~8x290cy of
// slack vs ~577cy DRAM latency). Steady chunks have ZERO clamp SELs and use
// immediate-offset loads from a per-chunk pointer (no per-load IMADs).
// body(s) consumes xv = x[s+1] (installs next body's layer-0 input).

#define TT 4096
#define BB 2048

__device__ __forceinline__ float tanhx(float x) {
    float y; asm("tanh.approx.f32 %0, %1;" : "=f"(y) : "f"(x)); return y;
}

__global__ __launch_bounds__(128) void lstm_kernel(
    const float* __restrict__ x,     // (T, B, 2)
    const float* __restrict__ h0g,   // (L, B, 4)
    const float* __restrict__ c0g,   // (L, B, 4)
    const float* __restrict__ Wih0,  // (16, 2)
    const float* __restrict__ Wr,    // (3, 16, 4)  W_ih layers 1..3
    const float* __restrict__ Whh,   // (4, 16, 4)
    const float* __restrict__ bih,   // (4, 16)
    const float* __restrict__ bhh,   // (4, 16)
    float* __restrict__ out)         // ys (T,B,4) ++ hT (L,B,4) ++ cT (L,B,4)
{
    const int lane  = threadIdx.x & 31;
    const int warp  = threadIdx.x >> 5;
    const int b     = lane >> 4;              // batch sub-index in warp 0..1
    const int l     = (lane >> 2) & 3;        // layer 0..3
    const int j     = lane & 3;               // hidden unit 0..3
    const int batch = blockIdx.x * 8 + warp * 2 + b;

    // handoff source lanes (previous layer's quad)
    const int ps0 = lane - 4;
    const int ps1 = (lane - 4) ^ 1;
    const int ps2 = (lane - 4) ^ 2;
    const int ps3 = (lane - 4) ^ 3;

    // ---- weights: 4 gate rows of unit j in layer l ----
    // pre-scale: sigmoid gates (i,f,o) -> 0.5 (sigmoid via tanh), g -> 1.
    float win[4][4], wh[4][4], bz[4];
#pragma unroll
    for (int g4 = 0; g4 < 4; g4++) {
        const int   row = g4 * 4 + j;         // i_j, f_j, g_j, o_j
        const float sc  = (g4 == 2) ? 1.0f : 0.5f;
        if (l == 0) {
            win[g4][0] = Wih0[row * 2 + 0] * sc;
            win[g4][1] = Wih0[row * 2 + 1] * sc;
            win[g4][2] = 0.f; win[g4][3] = 0.f;
        } else {
#pragma unroll
            for (int m = 0; m < 4; m++)
                win[g4][m] = Wr[((l - 1) * 16 + row) * 4 + (j ^ m)] * sc;
        }
#pragma unroll
        for (int m = 0; m < 4; m++)
            wh[g4][m] = Whh[(l * 16 + row) * 4 + (j ^ m)] * sc;
        bz[g4] = (bih[l * 16 + row] + bhh[l * 16 + row]) * sc;
    }

    // ---- states ----
    float hown[4], hin[4], c;
#pragma unroll
    for (int m = 0; m < 4; m++) {
        hown[m] = h0g[(l * BB + batch) * 4 + (j ^ m)];
        hin[m]  = 0.f;
    }
    c = c0g[(l * BB + batch) * 4 + j];

    float* __restrict__ hso = out + (size_t)TT * BB * 4;
    float* __restrict__ cso = hso + (size_t)4 * BB * 4;
    float4* __restrict__ ysp = reinterpret_cast<float4*>(out) + batch - 3 * BB;

    // ---- x bank: 8 slots, invariant at chunk top: xS[k] = x[s0+1+k] ----
    const float2* __restrict__ xb2 = reinterpret_cast<const float2*>(x) + batch;
    float2 xS[8];
#pragma unroll
    for (int k = 0; k < 8; k++) xS[k] = xb2[(size_t)(1 + k) * BB];
    if (l == 0) { hin[0] = xb2[0].x; hin[1] = xb2[0].y; }  // x[0] for body(0)

    auto body = [&](int s, float2 xv, bool masked) {
        // ---- four gate pre-activations (two depth-4 chains each) ----
        float z[4];
#pragma unroll
        for (int g4 = 0; g4 < 4; g4++) {
            float u = fmaf(win[g4][0], hin[0],
                      fmaf(win[g4][1], hin[1], bz[g4]));
            u = fmaf(win[g4][2], hin[2], u);
            u = fmaf(win[g4][3], hin[3], u);
            float v = fmaf(wh[g4][0], hown[0], wh[g4][1] * hown[1]);
            v = fmaf(wh[g4][2], hown[2], v);
            v = fmaf(wh[g4][3], hown[3], v);
            z[g4] = u + v;
        }

        // ---- activations (all MUFU tanh) ----
        float si = fmaf(tanhx(z[0]), 0.5f, 0.5f);   // sigma(i)
        float sf = fmaf(tanhx(z[1]), 0.5f, 0.5f);   // sigma(f)
        float tg = tanhx(z[2]);                     // tanh(g)
        float so = fmaf(tanhx(z[3]), 0.5f, 0.5f);   // sigma(o)

        float cn = fmaf(sf, c, si * tg);
        float th = tanhx(cn);                       // tanh(c)
        float h  = so * th;

        // ---- 7 independent shuffles, all sourced from h ----
        float h1 = __shfl_xor_sync(0xffffffffu, h, 1);
        float h2 = __shfl_xor_sync(0xffffffffu, h, 2);
        float h3 = __shfl_xor_sync(0xffffffffu, h, 3);
        float p0 = __shfl_sync(0xffffffffu, h, ps0, 16);
        float p1 = __shfl_sync(0xffffffffu, h, ps1, 16);
        float p2 = __shfl_sync(0xffffffffu, h, ps2, 16);
        float p3 = __shfl_sync(0xffffffffu, h, ps3, 16);

        bool act  = masked ? ((unsigned)(s - l)     < (unsigned)TT) : true;
        bool actp = masked ? ((unsigned)(s + 1 - l) < (unsigned)TT) : true;

        if (act) {
            c = cn;
            hown[0] = h;  hown[1] = h1; hown[2] = h2; hown[3] = h3;
        }
        if (l == 0) { hin[0] = xv.x; hin[1] = xv.y; }
        else if (actp) { hin[0] = p0; hin[1] = p1; hin[2] = p2; hin[3] = p3; }
        return act;
    };

    // ---- steady loop: chunks of 8 bodies; all prefetches in-bounds for
    // s0 <= TT-17 (loads reach x[s0+16]); loop runs s0 = 0..4072 ----
#pragma unroll 1
    for (int s0 = 0; s0 < TT - 16; s0 += 8) {
        const bool masked = (s0 == 0);
        const float2* __restrict__ xq = xb2 + (size_t)(s0 + 9) * BB;
#pragma unroll
        for (int k = 0; k < 8; k++) {
            float2 xv = xS[k];
            xS[k] = xq[(size_t)k * BB];       // imm-offset load, slack 8 bodies
            bool act = body(s0 + k, xv, masked);
            if (act && l == 3 && j == 0)
                ysp[(size_t)k * BB] = make_float4(hown[0], hown[1],
                                                  hown[2], hown[3]);
        }
        ysp += (size_t)8 * BB;
    }
    // ---- chunk s0 = TT-16: refill with clamped tail (x[TT-7..TT-1]) ----
    {
        const int s0 = TT - 16;
        const float2* __restrict__ xq = xb2 + (size_t)(s0 + 9) * BB;  // x[TT-7]
#pragma unroll
        for (int k = 0; k < 8; k++) {
            float2 xv = xS[k];
            xS[k] = xq[(size_t)((k < 6) ? k : 6) * BB];   // clamp to x[TT-1]
            body(s0 + k, xv, false);
            if (l == 3 && j == 0)
                ysp[(size_t)k * BB] = make_float4(hown[0], hown[1],
                                                  hown[2], hown[3]);
        }
        ysp += (size_t)8 * BB;
    }
    // ---- chunk s0 = TT-8: no loads (bank holds x[TT-7..TT-1]+clamp) ----
    {
        const int s0 = TT - 8;
#pragma unroll
        for (int k = 0; k < 8; k++) {
            body(s0 + k, xS[k], false);
            if (l == 3 && j == 0)
                ysp[(size_t)k * BB] = make_float4(hown[0], hown[1],
                                                  hown[2], hown[3]);
        }
        ysp += (size_t)8 * BB;
    }
    // ---- drain: bodies TT..TT+2 (layer 0 inactive) ----
#pragma unroll
    for (int d = 0; d < 3; d++) {
        bool act = body(TT + d, make_float2(0.f, 0.f), true);
        if (act && l == 3 && j == 0)
            ysp[(size_t)d * BB] = make_float4(hown[0], hown[1],
                                              hown[2], hown[3]);
    }

    // ---- final hT / cT ----
    if (j == 0)   // hown[m] = h_m natural order for j==0
        *reinterpret_cast<float4*>(hso + (l * BB + batch) * 4) =
            make_float4(hown[0], hown[1], hown[2], hown[3]);
    cso[(l * BB + batch) * 4 + j] = c;
}

extern "C" void kernel_launch(void* const* d_in, const int* in_sizes, int n_in,
                              void* d_out, int out_size) {
    (void)in_sizes; (void)n_in; (void)out_size;
    const float* x    = (const float*)d_in[0];
    const float* h0   = (const float*)d_in[1];
    const float* c0   = (const float*)d_in[2];
    const float* Wih0 = (const float*)d_in[3];
    const float* Wr   = (const float*)d_in[4];
    const float* Whh  = (const float*)d_in[5];
    const float* bih  = (const float*)d_in[6];
    const float* bhh  = (const float*)d_in[7];
    // 8 batches per block (4 warps x 2), 256 blocks
    lstm_kernel<<<BB / 8, 128>>>(x, h0, c0, Wih0, Wr, Whh, bih, bhh,
                                 (float*)d_out);
}

// round 16
// speedup vs baseline: 1.8574x; 1.0412x over previous
#include <cuda_runtime.h>

// LSTM T=4096, B=2048, I=2, H=4, L=4. Gate order i,f,g,o.
// lane = b*16 + l*4 + j; PLUS each thread carries CH=2 independent batch
// chains (weights shared) -> 4 batches/warp, 512 warps. The two chains
// interleave in the instruction stream and fill each other's dependency
// stalls (tanh/SHFL/FMA latencies), now that x loads are software-pipelined
// with 8-body slack (the R9 ILP retry failed only because of the broken
// x pipeline). All activations tanh.approx. Skewed wavefront: body(s) runs
// layer l at step s-l.

#define TT 4096
#define BB 2048
#define CH 2

__device__ __forceinline__ float tanhx(float x) {
    float y; asm("tanh.approx.f32 %0, %1;" : "=f"(y) : "f"(x)); return y;
}

__global__ __launch_bounds__(128) void lstm_kernel(
    const float* __restrict__ x,     // (T, B, 2)
    const float* __restrict__ h0g,   // (L, B, 4)
    const float* __restrict__ c0g,   // (L, B, 4)
    const float* __restrict__ Wih0,  // (16, 2)
    const float* __restrict__ Wr,    // (3, 16, 4)  W_ih layers 1..3
    const float* __restrict__ Whh,   // (4, 16, 4)
    const float* __restrict__ bih,   // (4, 16)
    const float* __restrict__ bhh,   // (4, 16)
    float* __restrict__ out)         // ys (T,B,4) ++ hT (L,B,4) ++ cT (L,B,4)
{
    const int lane   = threadIdx.x & 31;
    const int warp   = threadIdx.x >> 5;
    const int b      = lane >> 4;             // SIMD batch sub-index 0..1
    const int l      = (lane >> 2) & 3;       // layer 0..3
    const int j      = lane & 3;              // hidden unit 0..3
    const int batch0 = blockIdx.x * 16 + warp * 4 + b * 2;  // chains at +0,+1

    // handoff source lanes (previous layer's quad)
    const int ps0 = lane - 4;
    const int ps1 = (lane - 4) ^ 1;
    const int ps2 = (lane - 4) ^ 2;
    const int ps3 = (lane - 4) ^ 3;

    // ---- weights: 4 gate rows of unit j in layer l (shared by chains) ----
    // pre-scale: sigmoid gates (i,f,o) -> 0.5 (sigmoid via tanh), g -> 1.
    float win[4][4], wh[4][4], bz[4];
#pragma unroll
    for (int g4 = 0; g4 < 4; g4++) {
        const int   row = g4 * 4 + j;         // i_j, f_j, g_j, o_j
        const float sc  = (g4 == 2) ? 1.0f : 0.5f;
        if (l == 0) {
            win[g4][0] = Wih0[row * 2 + 0] * sc;
            win[g4][1] = Wih0[row * 2 + 1] * sc;
            win[g4][2] = 0.f; win[g4][3] = 0.f;
        } else {
#pragma unroll
            for (int m = 0; m < 4; m++)
                win[g4][m] = Wr[((l - 1) * 16 + row) * 4 + (j ^ m)] * sc;
        }
#pragma unroll
        for (int m = 0; m < 4; m++)
            wh[g4][m] = Whh[(l * 16 + row) * 4 + (j ^ m)] * sc;
        bz[g4] = (bih[l * 16 + row] + bhh[l * 16 + row]) * sc;
    }

    // ---- per-chain states ----
    float hown[CH][4], hin[CH][4], cst[CH];
#pragma unroll
    for (int ch = 0; ch < CH; ch++) {
        const int bt = batch0 + ch;
#pragma unroll
        for (int m = 0; m < 4; m++) {
            hown[ch][m] = h0g[(l * BB + bt) * 4 + (j ^ m)];
            hin[ch][m]  = 0.f;
        }
        cst[ch] = c0g[(l * BB + bt) * 4 + j];
    }

    float* __restrict__ hso = out + (size_t)TT * BB * 4;
    float* __restrict__ cso = hso + (size_t)4 * BB * 4;
    float4* __restrict__ ysp = reinterpret_cast<float4*>(out) + batch0 - 3 * BB;

    // ---- x banks: 8 slots per chain, xS[ch][k] = x[s0+1+k] for batch0+ch ----
    const float2* __restrict__ xb2 = reinterpret_cast<const float2*>(x) + batch0;
    float2 xS[CH][8];
#pragma unroll
    for (int k = 0; k < 8; k++) {
        xS[0][k] = xb2[(size_t)(1 + k) * BB];
        xS[1][k] = xb2[(size_t)(1 + k) * BB + 1];
    }
    if (l == 0) {
        hin[0][0] = xb2[0].x; hin[0][1] = xb2[0].y;
        hin[1][0] = xb2[1].x; hin[1][1] = xb2[1].y;
    }

    auto body = [&](int s, float2 xv0, float2 xv1, bool masked) {
        bool act  = masked ? ((unsigned)(s - l)     < (unsigned)TT) : true;
        bool actp = masked ? ((unsigned)(s + 1 - l) < (unsigned)TT) : true;

        float h[CH], h1[CH], h2[CH], h3[CH], p0[CH], p1[CH], p2[CH], p3[CH];

        // ---- both chains' compute, interleaved by the compiler ----
#pragma unroll
        for (int ch = 0; ch < CH; ch++) {
            float z[4];
#pragma unroll
            for (int g4 = 0; g4 < 4; g4++) {
                float u = fmaf(win[g4][0], hin[ch][0],
                          fmaf(win[g4][1], hin[ch][1], bz[g4]));
                u = fmaf(win[g4][2], hin[ch][2], u);
                u = fmaf(win[g4][3], hin[ch][3], u);
                float v = fmaf(wh[g4][0], hown[ch][0], wh[g4][1] * hown[ch][1]);
                v = fmaf(wh[g4][2], hown[ch][2], v);
                v = fmaf(wh[g4][3], hown[ch][3], v);
                z[g4] = u + v;
            }
            float si = fmaf(tanhx(z[0]), 0.5f, 0.5f);
            float sf = fmaf(tanhx(z[1]), 0.5f, 0.5f);
            float tg = tanhx(z[2]);
            float so = fmaf(tanhx(z[3]), 0.5f, 0.5f);
            float cn = fmaf(sf, cst[ch], si * tg);
            float th = tanhx(cn);
            h[ch] = so * th;
            if (act) cst[ch] = cn;
        }

        // ---- shuffles: 14 independent ops ----
#pragma unroll
        for (int ch = 0; ch < CH; ch++) {
            h1[ch] = __shfl_xor_sync(0xffffffffu, h[ch], 1);
            h2[ch] = __shfl_xor_sync(0xffffffffu, h[ch], 2);
            h3[ch] = __shfl_xor_sync(0xffffffffu, h[ch], 3);
            p0[ch] = __shfl_sync(0xffffffffu, h[ch], ps0, 16);
            p1[ch] = __shfl_sync(0xffffffffu, h[ch], ps1, 16);
            p2[ch] = __shfl_sync(0xffffffffu, h[ch], ps2, 16);
            p3[ch] = __shfl_sync(0xffffffffu, h[ch], ps3, 16);
        }

#pragma unroll
        for (int ch = 0; ch < CH; ch++) {
            if (act) {
                hown[ch][0] = h[ch];  hown[ch][1] = h1[ch];
                hown[ch][2] = h2[ch]; hown[ch][3] = h3[ch];
            }
            float2 xv = ch ? xv1 : xv0;
            if (l == 0) { hin[ch][0] = xv.x; hin[ch][1] = xv.y; }
            else if (actp) {
                hin[ch][0] = p0[ch]; hin[ch][1] = p1[ch];
                hin[ch][2] = p2[ch]; hin[ch][3] = p3[ch];
            }
        }
        return act;
    };

    auto store_ys = [&](size_t off) {
        if (l == 3 && j == 0) {
            ysp[off]     = make_float4(hown[0][0], hown[0][1],
                                       hown[0][2], hown[0][3]);
            ysp[off + 1] = make_float4(hown[1][0], hown[1][1],
                                       hown[1][2], hown[1][3]);
        }
    };

    // ---- steady loop: chunks of 8; prefetches in-bounds for s0 <= TT-17 ----
#pragma unroll 1
    for (int s0 = 0; s0 < TT - 16; s0 += 8) {
        const bool masked = (s0 == 0);
        const float2* __restrict__ xq = xb2 + (size_t)(s0 + 9) * BB;
#pragma unroll
        for (int k = 0; k < 8; k++) {
            float2 xv0 = xS[0][k], xv1 = xS[1][k];
            xS[0][k] = xq[(size_t)k * BB];
            xS[1][k] = xq[(size_t)k * BB + 1];
            bool act = body(s0 + k, xv0, xv1, masked);
            if (act) store_ys((size_t)k * BB);
        }
        ysp += (size_t)8 * BB;
    }
    // ---- chunk s0 = TT-16: refill with clamped tail ----
    {
        const int s0 = TT - 16;
        const float2* __restrict__ xq = xb2 + (size_t)(s0 + 9) * BB;  // x[TT-7]
#pragma unroll
        for (int k = 0; k < 8; k++) {
            float2 xv0 = xS[0][k], xv1 = xS[1][k];
            const size_t kk = (size_t)((k < 6) ? k : 6) * BB;
            xS[0][k] = xq[kk];
            xS[1][k] = xq[kk + 1];
            body(s0 + k, xv0, xv1, false);
            store_ys((size_t)k * BB);
        }
        ysp += (size_t)8 * BB;
    }
    // ---- chunk s0 = TT-8: no loads ----
    {
        const int s0 = TT - 8;
#pragma unroll
        for (int k = 0; k < 8; k++) {
            body(s0 + k, xS[0][k], xS[1][k], false);
            store_ys((size_t)k * BB);
        }
        ysp += (size_t)8 * BB;
    }
    // ---- drain: bodies TT..TT+2 ----
#pragma unroll
    for (int d = 0; d < 3; d++) {
        float2 zz = make_float2(0.f, 0.f);
        bool act = body(TT + d, zz, zz, true);
        if (act) store_ys((size_t)d * BB);
    }

    // ---- final hT / cT ----
#pragma unroll
    for (int ch = 0; ch < CH; ch++) {
        const int bt = batch0 + ch;
        if (j == 0)
            *reinterpret_cast<float4*>(hso + (l * BB + bt) * 4) =
                make_float4(hown[ch][0], hown[ch][1], hown[ch][2], hown[ch][3]);
        cso[(l * BB + bt) * 4 + j] = cst[ch];
    }
}

extern "C" void kernel_launch(void* const* d_in, const int* in_sizes, int n_in,
                              void* d_out, int out_size) {
    (void)in_sizes; (void)n_in; (void)out_size;
    const float* x    = (const float*)d_in[0];
    const float* h0   = (const float*)d_in[1];
    const float* c0   = (const float*)d_in[2];
    const float* Wih0 = (const float*)d_in[3];
    const float* Wr   = (const float*)d_in[4];
    const float* Whh  = (const float*)d_in[5];
    const float* bih  = (const float*)d_in[6];
    const float* bhh  = (const float*)d_in[7];
    // 16 batches per block (4 warps x 2 SIMD x 2 chains), 128 blocks
    lstm_kernel<<<BB / 16, 128>>>(x, h0, c0, Wih0, Wr, Whh, bih, bhh,
                                  (float*)d_out);
}

// round 17
// speedup vs baseline: 2.2965x; 1.2364x over previous
#include <cuda_runtime.h>

// LSTM T=4096, B=2048, I=2, H=4, L=4. Gate order i,f,g,o.
// lane = b*8 + l*2 + u : b = batch-in-warp (4), l = layer (4), u = half (2).
// Each thread owns 2 hidden units (8 gate rows): cell update thread-local for
// both units; loop-carried chain crosses ONE xor-1 shuffle. Layer-handoff
// shuffles have a full body of slack (skewed wavefront). z computed as packed
// f32x2 gate pairs {i,f},{g,o} per unit. All activations tanh.approx
// (sigmoid = 0.5*tanh(x/2)+0.5, weights pre-scaled 0.5).
// x pipeline: 8-slot register bank, load->use distance 8 bodies, imm-offset
// loads, zero clamp SELs in steady state (the R13/R15 fix).

#define TT 4096
#define BB 2048

typedef unsigned long long u64;

__device__ __forceinline__ float tanhx(float x) {
    float y; asm("tanh.approx.f32 %0, %1;" : "=f"(y) : "f"(x)); return y;
}
__device__ __forceinline__ u64 pack2(float lo, float hi) {
    u64 r; asm("mov.b64 %0, {%1, %2};" : "=l"(r) : "f"(lo), "f"(hi)); return r;
}
__device__ __forceinline__ u64 pdup(float v) {
    u64 r; asm("mov.b64 %0, {%1, %1};" : "=l"(r) : "f"(v)); return r;
}
__device__ __forceinline__ void unpack2(u64 v, float& lo, float& hi) {
    asm("mov.b64 {%0, %1}, %2;" : "=f"(lo), "=f"(hi) : "l"(v));
}
__device__ __forceinline__ u64 fma2(u64 a, u64 b, u64 c) {
    u64 d; asm("fma.rn.f32x2 %0, %1, %2, %3;" : "=l"(d) : "l"(a), "l"(b), "l"(c));
    return d;
}
__device__ __forceinline__ u64 mul2(u64 a, u64 b) {
    u64 d; asm("mul.rn.f32x2 %0, %1, %2;" : "=l"(d) : "l"(a), "l"(b));
    return d;
}
__device__ __forceinline__ u64 add2(u64 a, u64 b) {
    u64 d; asm("add.rn.f32x2 %0, %1, %2;" : "=l"(d) : "l"(a), "l"(b));
    return d;
}

__global__ __launch_bounds__(128) void lstm_kernel(
    const float* __restrict__ x,     // (T, B, 2)
    const float* __restrict__ h0g,   // (L, B, 4)
    const float* __restrict__ c0g,   // (L, B, 4)
    const float* __restrict__ Wih0,  // (16, 2)
    const float* __restrict__ Wr,    // (3, 16, 4)  W_ih layers 1..3
    const float* __restrict__ Whh,   // (4, 16, 4)
    const float* __restrict__ bih,   // (4, 16)
    const float* __restrict__ bhh,   // (4, 16)
    float* __restrict__ out)         // ys (T,B,4) ++ hT (L,B,4) ++ cT (L,B,4)
{
    const int lane  = threadIdx.x & 31;
    const int warp  = threadIdx.x >> 5;
    const int b     = lane >> 3;              // batch-in-warp 0..3
    const int l     = (lane >> 1) & 3;        // layer 0..3
    const int u     = lane & 1;               // half: units {2u, 2u+1}
    const int batch = blockIdx.x * 16 + warp * 4 + b;

    const bool l0 = (l == 0);
    const bool l3 = (l == 3);

    // layer-handoff source lanes (prev layer's two halves)
    const int ps0 = (lane - 2 - u) & 31;      // u=0 lane of layer l-1
    const int ps1 = (ps0 + 1) & 31;           // u=1 lane of layer l-1

    // ---- packed weights: [local unit u_][gate pair t][input k] ----
    // t=0 -> (i,f) both sigmoid (scale 0.5); t=1 -> (g,o) = (1.0, 0.5).
    // wh columns permuted so k indexes {own_lo, own_hi, partner_lo, partner_hi};
    // win natural order (handoff q0..q3 in unit order); l==0: k=0,1 carry Wih0.
    u64 winP[2][2][4], whP[2][2][4], bzP[2][2];
#pragma unroll
    for (int u_ = 0; u_ < 2; u_++) {
        const int j = 2 * u + u_;             // global unit
#pragma unroll
        for (int t = 0; t < 2; t++) {
            const int   rA = (t ? 8 : 0) + j;   // i_j or g_j
            const int   rB = (t ? 12 : 4) + j;  // f_j or o_j
            const float sA = t ? 1.0f : 0.5f;
            const float sB = 0.5f;
#pragma unroll
            for (int k = 0; k < 4; k++) {
                const int col = (k < 2) ? (2 * u + k) : (2 * (1 - u) + (k - 2));
                whP[u_][t][k] = pack2(Whh[(l * 16 + rA) * 4 + col] * sA,
                                      Whh[(l * 16 + rB) * 4 + col] * sB);
                float wa, wb;
                if (!l0) {
                    wa = Wr[((l - 1) * 16 + rA) * 4 + k] * sA;
                    wb = Wr[((l - 1) * 16 + rB) * 4 + k] * sB;
                } else if (k < 2) {
                    wa = Wih0[rA * 2 + k] * sA;
                    wb = Wih0[rB * 2 + k] * sB;
                } else {
                    wa = 0.f; wb = 0.f;
                }
                winP[u_][t][k] = pack2(wa, wb);
            }
            bzP[u_][t] = pack2((bih[l * 16 + rA] + bhh[l * 16 + rA]) * sA,
                               (bih[l * 16 + rB] + bhh[l * 16 + rB]) * sB);
        }
    }

    // ---- states: this thread's two units ----
    float h_lo, h_hi, c_lo, c_hi;
    {
        float2 hv = *reinterpret_cast<const float2*>(
            h0g + (l * BB + batch) * 4 + 2 * u);
        h_lo = hv.x; h_hi = hv.y;
        float2 cv = *reinterpret_cast<const float2*>(
            c0g + (l * BB + batch) * 4 + 2 * u);
        c_lo = cv.x; c_hi = cv.y;
    }

    float* __restrict__ hso = out + (size_t)TT * BB * 4;
    float* __restrict__ cso = hso + (size_t)4 * BB * 4;
    float2* __restrict__ ysp =
        reinterpret_cast<float2*>(out) + (size_t)batch * 2 + u - (size_t)3 * BB * 2;

    // ---- x bank: 8 slots, invariant at chunk top: xS[k] = x[s0+1+k] ----
    const float2* __restrict__ xb2 = reinterpret_cast<const float2*>(x) + batch;
    float2 xS[8];
#pragma unroll
    for (int k = 0; k < 8; k++) xS[k] = xb2[(size_t)(1 + k) * BB];
    const float2 x0v = xb2[0];

    // ---- pre-loop: populate hP / hinP from initial state (x[0] for l0) ----
    u64 hP[4], hinP[4];
    {
        float plo = __shfl_xor_sync(0xffffffffu, h_lo, 1);
        float phi = __shfl_xor_sync(0xffffffffu, h_hi, 1);
        float q0  = __shfl_sync(0xffffffffu, h_lo, ps0, 32);
        float q1  = __shfl_sync(0xffffffffu, h_hi, ps0, 32);
        float q2  = __shfl_sync(0xffffffffu, h_lo, ps1, 32);
        float q3  = __shfl_sync(0xffffffffu, h_hi, ps1, 32);
        hP[0] = pdup(h_lo); hP[1] = pdup(h_hi);
        hP[2] = pdup(plo);  hP[3] = pdup(phi);
        hinP[0] = pdup(l0 ? x0v.x : q0);
        hinP[1] = pdup(l0 ? x0v.y : q1);
        hinP[2] = pdup(q2); hinP[3] = pdup(q3);
    }

    // body(s): consumes xv = x[s+1] (installs next body's layer-0 input)
    auto body = [&](int s, float2 xv, bool masked) {
        bool act = masked ? ((unsigned)(s - l) < (unsigned)TT) : true;

        // ---- z pre-activations: 4 packed gate pairs ----
        float zi[2], zf[2], zg[2], zo[2];
#pragma unroll
        for (int u_ = 0; u_ < 2; u_++) {
#pragma unroll
            for (int t = 0; t < 2; t++) {
                u64 uu = bzP[u_][t];
#pragma unroll
                for (int k = 0; k < 4; k++)
                    uu = fma2(winP[u_][t][k], hinP[k], uu);
                u64 vv = mul2(whP[u_][t][0], hP[0]);
#pragma unroll
                for (int k = 1; k < 4; k++)
                    vv = fma2(whP[u_][t][k], hP[k], vv);
                float a2, b2;
                unpack2(add2(uu, vv), a2, b2);
                if (t == 0) { zi[u_] = a2; zf[u_] = b2; }
                else        { zg[u_] = a2; zo[u_] = b2; }
            }
        }

        // ---- activations + cell updates (both units thread-local) ----
        float cn_lo, cn_hi, hn_lo, hn_hi;
        {
            float si = fmaf(tanhx(zi[0]), 0.5f, 0.5f);
            float sf = fmaf(tanhx(zf[0]), 0.5f, 0.5f);
            float tg = tanhx(zg[0]);
            float so = fmaf(tanhx(zo[0]), 0.5f, 0.5f);
            cn_lo = fmaf(sf, c_lo, si * tg);
            hn_lo = so * tanhx(cn_lo);
        }
        {
            float si = fmaf(tanhx(zi[1]), 0.5f, 0.5f);
            float sf = fmaf(tanhx(zf[1]), 0.5f, 0.5f);
            float tg = tanhx(zg[1]);
            float so = fmaf(tanhx(zo[1]), 0.5f, 0.5f);
            cn_hi = fmaf(sf, c_hi, si * tg);
            hn_hi = so * tanhx(cn_hi);
        }

        if (act) {
            c_lo = cn_lo; c_hi = cn_hi;
            h_lo = hn_lo; h_hi = hn_hi;
        }

        // ---- shuffles (handoff has a full body of slack) ----
        float plo = __shfl_xor_sync(0xffffffffu, h_lo, 1);
        float phi = __shfl_xor_sync(0xffffffffu, h_hi, 1);
        float q0  = __shfl_sync(0xffffffffu, h_lo, ps0, 32);
        float q1  = __shfl_sync(0xffffffffu, h_hi, ps0, 32);
        float q2  = __shfl_sync(0xffffffffu, h_lo, ps1, 32);
        float q3  = __shfl_sync(0xffffffffu, h_hi, ps1, 32);

        hP[0] = pdup(h_lo); hP[1] = pdup(h_hi);
        hP[2] = pdup(plo);  hP[3] = pdup(phi);
        hinP[0] = pdup(l0 ? xv.x : q0);
        hinP[1] = pdup(l0 ? xv.y : q1);
        hinP[2] = pdup(q2); hinP[3] = pdup(q3);
        return act;
    };

    // ---- steady loop: chunks of 8; prefetches in-bounds for s0 <= TT-17 ----
#pragma unroll 1
    for (int s0 = 0; s0 < TT - 16; s0 += 8) {
        const bool masked = (s0 == 0);
        const float2* __restrict__ xq = xb2 + (size_t)(s0 + 9) * BB;
#pragma unroll
        for (int k = 0; k < 8; k++) {
            float2 xv = xS[k];
            xS[k] = xq[(size_t)k * BB];       // imm-offset load, slack 8 bodies
            bool act = body(s0 + k, xv, masked);
            if (act && l3)
                ysp[(size_t)k * BB * 2] = make_float2(h_lo, h_hi);
        }
        ysp += (size_t)8 * BB * 2;
    }
    // ---- chunk s0 = TT-16: refill with clamped tail (x[TT-7..TT-1]) ----
    {
        const int s0 = TT - 16;
        const float2* __restrict__ xq = xb2 + (size_t)(s0 + 9) * BB;  // x[TT-7]
#pragma unroll
        for (int k = 0; k < 8; k++) {
            float2 xv = xS[k];
            xS[k] = xq[(size_t)((k < 6) ? k : 6) * BB];   // clamp to x[TT-1]
            body(s0 + k, xv, false);
            if (l3) ysp[(size_t)k * BB * 2] = make_float2(h_lo, h_hi);
        }
        ysp += (size_t)8 * BB * 2;
    }
    // ---- chunk s0 = TT-8: no loads (bank holds x[TT-7..TT-1]+clamp) ----
    {
        const int s0 = TT - 8;
#pragma unroll
        for (int k = 0; k < 8; k++) {
            body(s0 + k, xS[k], false);
            if (l3) ysp[(size_t)k * BB * 2] = make_float2(h_lo, h_hi);
        }
        ysp += (size_t)8 * BB * 2;
    }
    // ---- drain: bodies TT..TT+2 (layer 0 inactive) ----
#pragma unroll
    for (int d = 0; d < 3; d++) {
        bool act = body(TT + d, make_float2(0.f, 0.f), true);
        if (act && l3)
            ysp[(size_t)d * BB * 2] = make_float2(h_lo, h_hi);
    }

    // ---- final hT / cT (each lane stores its 2 units) ----
    *reinterpret_cast<float2*>(hso + (l * BB + batch) * 4 + 2 * u) =
        make_float2(h_lo, h_hi);
    *reinterpret_cast<float2*>(cso + (l * BB + batch) * 4 + 2 * u) =
        make_float2(c_lo, c_hi);
}

extern "C" void kernel_launch(void* const* d_in, const int* in_sizes, int n_in,
                              void* d_out, int out_size) {
    (void)in_sizes; (void)n_in; (void)out_size;
    const float* x    = (const float*)d_in[0];
    const float* h0   = (const float*)d_in[1];
    const float* c0   = (const float*)d_in[2];
    const float* Wih0 = (const float*)d_in[3];
    const float* Wr   = (const float*)d_in[4];
    const float* Whh  = (const float*)d_in[5];
    const float* bih  = (const float*)d_in[6];
    const float* bhh  = (const float*)d_in[7];
    // 16 batches per block (4 warps x 4), 128 blocks -> 512 warps
    lstm_kernel<<<BB / 16, 128>>>(x, h0, c0, Wih0, Wr, Whh, bih, bhh,
                                  (float*)d_out);
}